// round 6
// baseline (speedup 1.0000x reference)
#include <cuda_runtime.h>
#include <cstdint>

// Problem shape (fixed by the dataset)
#define BATCH 1024
#define NBLK  1024
#define DIN   64
#define DOUT  64
#define BM    128          // batch rows per CTA
#define THREADS 256

// smem strides (words). XS_S=66: 4*66 mod 32 = 8 -> the 4 row addresses a warp
// reads per k map to distinct banks. WT_S=66: 8B-aligned rows for LDS.64.
#define XS_S 66
#define WT_S 66

__device__ __forceinline__ uint64_t pack_dup(float a) {
    uint32_t au = __float_as_uint(a);
    uint64_t r;
    asm("mov.b64 %0, {%1, %1};" : "=l"(r) : "r"(au));
    return r;
}
__device__ __forceinline__ uint64_t pack2(float lo, float hi) {
    uint32_t l = __float_as_uint(lo), h = __float_as_uint(hi);
    uint64_t r;
    asm("mov.b64 %0, {%1, %2};" : "=l"(r) : "r"(l), "r"(h));
    return r;
}
__device__ __forceinline__ void unpack2(uint64_t v, float& lo, float& hi) {
    uint32_t l, h;
    asm("mov.b64 {%0, %1}, %2;" : "=r"(l), "=r"(h) : "l"(v));
    lo = __uint_as_float(l);
    hi = __uint_as_float(h);
}
__device__ __forceinline__ void fma_f32x2(uint64_t& d, uint64_t a, uint64_t b) {
    asm("fma.rn.f32x2 %0, %1, %2, %0;" : "+l"(d) : "l"(a), "l"(b));
}

__global__ __launch_bounds__(THREADS, 3)
void block_linear_kernel(const float* __restrict__ x,
                         const float* __restrict__ W,
                         const float* __restrict__ bias,
                         float* __restrict__ out) {
    __shared__ float xs[BM * XS_S];       // x tile [128][64], stride 66
    __shared__ float wt[DIN * WT_S];      // W[n] transposed: wt[k][o], stride 66
    __shared__ float bs[DOUT];

    const int n  = blockIdx.y;
    const int b0 = blockIdx.x * BM;
    const int tid = threadIdx.x;

    // ---- load W[n] (64x64 fp32, row o contiguous over i) transposed into wt[k][o]
    {
        const float4* Wg = (const float4*)(W + (size_t)n * (DOUT * DIN));
        #pragma unroll
        for (int t = tid; t < (DOUT * DIN) / 4; t += THREADS) {
            int o  = t >> 4;      // 0..63
            int i4 = t & 15;      // 0..15
            float4 v = Wg[t];
            wt[(i4 * 4 + 0) * WT_S + o] = v.x;
            wt[(i4 * 4 + 1) * WT_S + o] = v.y;
            wt[(i4 * 4 + 2) * WT_S + o] = v.z;
            wt[(i4 * 4 + 3) * WT_S + o] = v.w;
        }
        if (tid < DOUT) bs[tid] = bias[(size_t)n * DOUT + tid];
    }

    // ---- load x tile: rows b0..b0+127, 64 floats each (row stride NBLK*DIN in gmem)
    {
        #pragma unroll
        for (int t = tid; t < BM * (DIN / 2); t += THREADS) {
            int r  = t >> 5;      // 0..127
            int i2 = t & 31;      // 0..31 (float2 index)
            const float2* xg = (const float2*)(x + ((size_t)(b0 + r) * NBLK + n) * DIN);
            float2 v = xg[i2];
            // row offset 66*4=264B -> 8B aligned, float2 store OK
            *(float2*)&xs[r * XS_S + i2 * 2] = v;
        }
    }
    __syncthreads();

    // ---- per-thread 4x8 micro-tile as 4x4 f32x2 accumulators
    const int tx = tid & 7;           // column group: cols tx*8 .. tx*8+7
    const int ty = tid >> 3;          // row group:    rows ty*4 .. ty*4+3
    const int cb = tx * 8;
    const int rb = ty * 4;

    uint64_t acc[4][4];
    #pragma unroll
    for (int r = 0; r < 4; r++)
        #pragma unroll
        for (int c = 0; c < 4; c++)
            acc[r][c] = pack2(bs[cb + 2 * c], bs[cb + 2 * c + 1]);

    #pragma unroll 16
    for (int k = 0; k < DIN; k++) {
        uint64_t wv[4];
        const float* wrow = &wt[k * WT_S + cb];
        #pragma unroll
        for (int c = 0; c < 4; c++)
            wv[c] = *(const uint64_t*)&wrow[2 * c];

        #pragma unroll
        for (int r = 0; r < 4; r++) {
            uint64_t a2 = pack_dup(xs[(rb + r) * XS_S + k]);
            #pragma unroll
            for (int c = 0; c < 4; c++)
                fma_f32x2(acc[r][c], a2, wv[c]);
        }
    }

    // ---- epilogue: out[(b0+rb+r)*NBLK*DOUT ... ] layout [B][NB][DOUT]
    #pragma unroll
    for (int r = 0; r < 4; r++) {
        float* orow = out + ((size_t)(b0 + rb + r) * NBLK + n) * DOUT + cb;
        #pragma unroll
        for (int c = 0; c < 4; c++) {
            float lo, hi;
            unpack2(acc[r][c], lo, hi);
            *(float2*)&orow[2 * c] = make_float2(lo, hi);
        }
    }
}

extern "C" void kernel_launch(void* const* d_in, const int* in_sizes, int n_in,
                              void* d_out, int out_size) {
    const float* x = (const float*)d_in[0];
    const float* W = (const float*)d_in[1];
    const float* b = (const float*)d_in[2];
    float* out = (float*)d_out;

    dim3 grid(BATCH / BM, NBLK);
    block_linear_kernel<<<grid, THREADS>>>(x, W, b, out);
}

// round 8
// speedup vs baseline: 1.6646x; 1.6646x over previous
#include <cuda_runtime.h>
#include <cstdint>

// Problem shape (fixed by the dataset)
#define BATCH 1024
#define NBLK  1024
#define DIN   64
#define DOUT  64
#define BM    128          // batch rows per CTA
#define THREADS 256

__device__ __forceinline__ uint64_t pack_dup(float a) {
    uint32_t au = __float_as_uint(a);
    uint64_t r;
    asm("mov.b64 %0, {%1, %1};" : "=l"(r) : "r"(au));
    return r;
}
__device__ __forceinline__ uint64_t pack2(float lo, float hi) {
    uint32_t l = __float_as_uint(lo), h = __float_as_uint(hi);
    uint64_t r;
    asm("mov.b64 %0, {%1, %2};" : "=l"(r) : "r"(l), "r"(h));
    return r;
}
__device__ __forceinline__ void unpack2(uint64_t v, float& lo, float& hi) {
    uint32_t l, h;
    asm("mov.b64 {%0, %1}, %2;" : "=r"(l), "=r"(h) : "l"(v));
    lo = __uint_as_float(l);
    hi = __uint_as_float(h);
}
__device__ __forceinline__ void fma_f32x2(uint64_t& d, uint64_t a, uint64_t b) {
    asm("fma.rn.f32x2 %0, %1, %2, %0;" : "+l"(d) : "l"(a), "l"(b));
}

// Shared layout (both tiles swizzled at 16B-chunk granularity, stride 64 floats):
//   xs: element (r,k) at  r*64 + ((k>>2 ^ (2*((r>>2)&3)))<<2 | (k&3))
//       -> the 4 rows a warp reads per LDS.128 hit disjoint bank quads.
//   wt: element (k,o) at  k*64 + (((o>>2) ^ (k>>2))<<2 | (o&3))
//       -> mainloop LDS.128 of a 64-float w-row = 2 conflict-free wavefronts,
//          and the transpose STS.32s are only 2-way instead of 16-way.
// Total static smem = 32KB + 16KB = 48KB exactly (bias read via LDG).

__global__ __launch_bounds__(THREADS, 3)
void block_linear_kernel(const float* __restrict__ x,
                         const float* __restrict__ W,
                         const float* __restrict__ bias,
                         float* __restrict__ out) {
    __shared__ float xs[BM * DIN];     // 32 KB
    __shared__ float wt[DIN * DOUT];   // 16 KB

    const int n   = blockIdx.y;
    const int b0  = blockIdx.x * BM;
    const int tid = threadIdx.x;

    // ---- W[n] (row o contiguous over i) -> transposed + swizzled wt
    {
        const float4* Wg = (const float4*)(W + (size_t)n * (DOUT * DIN));
        #pragma unroll
        for (int t = tid; t < (DOUT * DIN) / 4; t += THREADS) {
            int o  = t >> 4;      // 0..63
            int i4 = t & 15;      // k>>2, 0..15
            float4 v = Wg[t];
            int og = o >> 2, ol = o & 3;
            int base = (i4 * 4) * 64 + (((og ^ i4) << 2) | ol);
            wt[base + 0 * 64] = v.x;
            wt[base + 1 * 64] = v.y;
            wt[base + 2 * 64] = v.z;
            wt[base + 3 * 64] = v.w;
        }
    }

    // ---- x tile: rows b0..b0+127, swizzled 16B chunks
    {
        #pragma unroll
        for (int t = tid; t < BM * (DIN / 4); t += THREADS) {
            int r  = t >> 4;      // 0..127
            int c4 = t & 15;      // 16B chunk index
            const float4* xg = (const float4*)(x + ((size_t)(b0 + r) * NBLK + n) * DIN);
            float4 v = xg[c4];
            int swz = 2 * ((r >> 2) & 3);
            *(float4*)&xs[r * 64 + ((c4 ^ swz) << 2)] = v;
        }
    }
    __syncthreads();

    // ---- per-thread 4x8 micro-tile: rows rb..rb+3, cols {co1..co1+3, co2..co2+3}
    const int tx  = tid & 7;
    const int ty  = tid >> 3;
    const int rb  = ty * 4;
    const int swz = 2 * (ty & 3);     // == 2*(((rb+r)>>2)&3) for r<4
    const int co1 = tx * 4;
    const int co2 = 32 + tx * 4;

    uint64_t acc[4][4];
    {
        const float4 ba = *(const float4*)(bias + (size_t)n * DOUT + co1);
        const float4 bb = *(const float4*)(bias + (size_t)n * DOUT + co2);
        #pragma unroll
        for (int r = 0; r < 4; r++) {
            acc[r][0] = pack2(ba.x, ba.y);
            acc[r][1] = pack2(ba.z, ba.w);
            acc[r][2] = pack2(bb.x, bb.y);
            acc[r][3] = pack2(bb.z, bb.w);
        }
    }

    #pragma unroll 4
    for (int kc = 0; kc < 16; kc++) {
        float xv[4][4];
        #pragma unroll
        for (int r = 0; r < 4; r++)
            *(float4*)xv[r] = *(const float4*)&xs[(rb + r) * 64 + ((kc ^ swz) << 2)];

        #pragma unroll
        for (int kk = 0; kk < 4; kk++) {
            const int k = kc * 4 + kk;
            const float4 wa = *(const float4*)&wt[k * 64 + ((tx ^ kc) << 2)];
            const float4 wb = *(const float4*)&wt[k * 64 + (((tx + 8) ^ kc) << 2)];
            uint64_t w0 = pack2(wa.x, wa.y);
            uint64_t w1 = pack2(wa.z, wa.w);
            uint64_t w2 = pack2(wb.x, wb.y);
            uint64_t w3 = pack2(wb.z, wb.w);
            #pragma unroll
            for (int r = 0; r < 4; r++) {
                uint64_t a2 = pack_dup(xv[r][kk]);
                fma_f32x2(acc[r][0], a2, w0);
                fma_f32x2(acc[r][1], a2, w1);
                fma_f32x2(acc[r][2], a2, w2);
                fma_f32x2(acc[r][3], a2, w3);
            }
        }
    }

    // ---- epilogue: out layout [B][NB][DOUT]
    #pragma unroll
    for (int r = 0; r < 4; r++) {
        float* orow = out + ((size_t)(b0 + rb + r) * NBLK + n) * DOUT;
        float4 v;
        unpack2(acc[r][0], v.x, v.y);
        unpack2(acc[r][1], v.z, v.w);
        *(float4*)(orow + co1) = v;
        unpack2(acc[r][2], v.x, v.y);
        unpack2(acc[r][3], v.z, v.w);
        *(float4*)(orow + co2) = v;
    }
}

extern "C" void kernel_launch(void* const* d_in, const int* in_sizes, int n_in,
                              void* d_out, int out_size) {
    const float* x = (const float*)d_in[0];
    const float* W = (const float*)d_in[1];
    const float* b = (const float*)d_in[2];
    float* out = (float*)d_out;

    dim3 grid(BATCH / BM, NBLK);
    block_linear_kernel<<<grid, THREADS>>>(x, W, b, out);
}

// round 11
// speedup vs baseline: 1.6772x; 1.0075x over previous
#include <cuda_runtime.h>
#include <cstdint>

// Problem shape (fixed)
#define BATCH 1024
#define NBLK  1024
#define DIN   64
#define DOUT  64
#define BM    128
#define THREADS 256

// Dynamic smem layout, in float words:
//   xs : [128][68]  raw fp32 x tile        (stride 68 -> A-frag LDS conflict-free)
//   whi: [64][72]   W hi pairs, per o: 8 s-chunks x 4 float2 (k, k+4)
//   wlo: [64][72]   W lo pairs, same layout (stride 72 -> B-frag LDS.64 conflict-free)
#define XS_OFF   0
#define XS_S     68
#define WHI_OFF  (BM * XS_S)                 // 8704
#define W_S      72
#define WLO_OFF  (WHI_OFF + DOUT * W_S)      // 13312
#define SMEM_WORDS (WLO_OFF + DOUT * W_S)    // 17920 words
#define SMEM_BYTES (SMEM_WORDS * 4)          // 71680 B

static __device__ __forceinline__ float tf32_rna(float v) {
    uint32_t u;
    asm("cvt.rna.tf32.f32 %0, %1;" : "=r"(u) : "f"(v));
    return __uint_as_float(u);
}

static __device__ __forceinline__ void mma_tf32(float4& d,
                                                uint32_t a0, uint32_t a1,
                                                uint32_t a2, uint32_t a3,
                                                uint32_t b0, uint32_t b1) {
    asm volatile(
        "mma.sync.aligned.m16n8k8.row.col.f32.tf32.tf32.f32 "
        "{%0,%1,%2,%3}, {%4,%5,%6,%7}, {%8,%9}, {%0,%1,%2,%3};"
        : "+f"(d.x), "+f"(d.y), "+f"(d.z), "+f"(d.w)
        : "r"(a0), "r"(a1), "r"(a2), "r"(a3), "r"(b0), "r"(b1));
}

__global__ __launch_bounds__(THREADS, 3)
void block_linear_mma(const float* __restrict__ x,
                      const float* __restrict__ W,
                      const float* __restrict__ bias,
                      float* __restrict__ out) {
    extern __shared__ float sm[];

    const int n   = blockIdx.y;
    const int b0  = blockIdx.x * BM;
    const int tid = threadIdx.x;
    const int wid  = tid >> 5;
    const int lane = tid & 31;

    // ---- stage x tile [128 rows x 64 k], raw fp32, stride 68
    {
        #pragma unroll
        for (int it = 0; it < 8; it++) {
            int idx = tid + it * THREADS;      // 0..2047 float4 slots
            int m   = idx >> 4;
            int c4  = idx & 15;
            float4 v = *(const float4*)(x + ((size_t)(b0 + m) * NBLK + n) * DIN + c4 * 4);
            *(float4*)&sm[XS_OFF + m * XS_S + c4 * 4] = v;   // 272B row stride, 16B aligned
        }
    }

    // ---- stage W[n]: split tf32 hi/lo, packed as (k, k+4) float2 pairs
    {
        #pragma unroll
        for (int it = 0; it < 2; it++) {
            int ch = tid + it * THREADS;       // 0..511 : (o, s) chunks
            int o  = ch >> 3;
            int s  = ch & 7;
            const float* wrow = W + (size_t)n * (DOUT * DIN) + o * DIN + s * 8;
            float4 va = *(const float4*)(wrow);       // k = 8s .. 8s+3
            float4 vb = *(const float4*)(wrow + 4);   // k = 8s+4 .. 8s+7
            float ha[4] = { tf32_rna(va.x), tf32_rna(va.y), tf32_rna(va.z), tf32_rna(va.w) };
            float hb[4] = { tf32_rna(vb.x), tf32_rna(vb.y), tf32_rna(vb.z), tf32_rna(vb.w) };
            float la[4] = { tf32_rna(va.x - ha[0]), tf32_rna(va.y - ha[1]),
                            tf32_rna(va.z - ha[2]), tf32_rna(va.w - ha[3]) };
            float lb[4] = { tf32_rna(vb.x - hb[0]), tf32_rna(vb.y - hb[1]),
                            tf32_rna(vb.z - hb[2]), tf32_rna(vb.w - hb[3]) };
            float* ph = &sm[WHI_OFF + o * W_S + s * 8];
            float* pl = &sm[WLO_OFF + o * W_S + s * 8];
            #pragma unroll
            for (int c = 0; c < 4; c++) {
                *(float2*)(ph + 2 * c) = make_float2(ha[c], hb[c]);   // (b0,b1) pair
                *(float2*)(pl + 2 * c) = make_float2(la[c], lb[c]);
            }
        }
    }
    __syncthreads();

    // ---- per-warp: rows m0..m0+15, all 64 cols as 8 n-tiles of m16n8k8
    const int m0 = wid * 16;
    const int gr = lane >> 2;     // A row group / B col group / D row group
    const int c  = lane & 3;      // A col / B row(k) / D col pair index

    float4 acc[8];
    #pragma unroll
    for (int j = 0; j < 8; j++) acc[j] = make_float4(0.f, 0.f, 0.f, 0.f);

    const float* xa0 = &sm[XS_OFF + (m0 + gr)     * XS_S + c];
    const float* xa1 = &sm[XS_OFF + (m0 + gr + 8) * XS_S + c];

    #pragma unroll
    for (int s = 0; s < 8; s++) {
        // A fragment (rows gr/gr+8, cols 8s+c / 8s+c+4), split hi/lo in regs
        float ra0 = xa0[8 * s],     ra1 = xa1[8 * s];
        float ra2 = xa0[8 * s + 4], ra3 = xa1[8 * s + 4];
        float h0 = tf32_rna(ra0), h1 = tf32_rna(ra1);
        float h2 = tf32_rna(ra2), h3 = tf32_rna(ra3);
        uint32_t ah0 = __float_as_uint(h0), ah1 = __float_as_uint(h1);
        uint32_t ah2 = __float_as_uint(h2), ah3 = __float_as_uint(h3);
        uint32_t al0 = __float_as_uint(tf32_rna(ra0 - h0));
        uint32_t al1 = __float_as_uint(tf32_rna(ra1 - h1));
        uint32_t al2 = __float_as_uint(tf32_rna(ra2 - h2));
        uint32_t al3 = __float_as_uint(tf32_rna(ra3 - h3));

        #pragma unroll
        for (int j = 0; j < 8; j++) {
            const int bo = (8 * j + gr) * W_S + s * 8 + 2 * c;
            uint2 bh = *(const uint2*)&sm[WHI_OFF + bo];   // (b0, b1) = (k=c, k=c+4)
            uint2 bl = *(const uint2*)&sm[WLO_OFF + bo];
            mma_tf32(acc[j], ah0, ah1, ah2, ah3, bh.x, bh.y);
            mma_tf32(acc[j], al0, al1, al2, al3, bh.x, bh.y);
            mma_tf32(acc[j], ah0, ah1, ah2, ah3, bl.x, bl.y);
        }
    }

    // ---- epilogue: D rows gr / gr+8, cols 8j + 2c, 2c+1 ; add bias, STG.64
    {
        float* orow0 = out + ((size_t)(b0 + m0 + gr)     * NBLK + n) * DOUT;
        float* orow1 = out + ((size_t)(b0 + m0 + gr + 8) * NBLK + n) * DOUT;
        const float2* bv = (const float2*)(bias + (size_t)n * DOUT);
        #pragma unroll
        for (int j = 0; j < 8; j++) {
            int col = 8 * j + 2 * c;
            float2 bb = __ldg(&bv[col >> 1]);
            *(float2*)(orow0 + col) = make_float2(acc[j].x + bb.x, acc[j].y + bb.y);
            *(float2*)(orow1 + col) = make_float2(acc[j].z + bb.x, acc[j].w + bb.y);
        }
    }
}

extern "C" void kernel_launch(void* const* d_in, const int* in_sizes, int n_in,
                              void* d_out, int out_size) {
    const float* x = (const float*)d_in[0];
    const float* W = (const float*)d_in[1];
    const float* b = (const float*)d_in[2];
    float* out = (float*)d_out;

    cudaFuncSetAttribute(block_linear_mma,
                         cudaFuncAttributeMaxDynamicSharedMemorySize, SMEM_BYTES);

    dim3 grid(BATCH / BM, NBLK);
    block_linear_mma<<<grid, THREADS, SMEM_BYTES>>>(x, W, b, out);
}